// round 10
// baseline (speedup 1.0000x reference)
#include <cuda_runtime.h>

#define Bn   8
#define Cin  64
#define Hh   128
#define Ww   128
#define HW   (Hh*Ww)
#define Cout 64
#define CIN2 66
#define KDIM 594    // CIN2 * 9
#define CHOM 27
#define NCHUNK 17   // 16 chunks x 4 ch + 1 chunk (coord ch 64,65 + pad)
#define KPAD 612    // 17 * 36

// ---------------- scratch ----------------
__device__ float g_wt[KPAD*Cout];   // transposed main weight [k][o], zero-padded

__global__ void prep_wt_kernel(const float* __restrict__ w)
{
    int i = blockIdx.x * 256 + threadIdx.x;
    if (i < KPAD * Cout) {
        int k = i >> 6;
        int o = i & 63;
        g_wt[i] = (k < KDIM) ? w[o * KDIM + k] : 0.0f;
    }
}

// ---------------- fused kernel ----------------
// One block per (row y, batch b); 384 threads.
// Phase B: om conv, 6 c-groups (11 ch) x 64 threads; thread = 2 px x 28 oc.
// Phase C: packed corner tables (sWt float4 + sPk packed int).
// Phase D: consumers = warps 0-3 (16oc x 4px each), producers = warps 4-11
//          (256 thr, pixel px = ptid&127, channel-half = ptid>>7).
// Smem floats: region reuse — B: sw[0,16632) rows[16632,21384) omb[21384,24840)
//              C/D: sWt[0,4608) sPk[4608,5760) cols[5760,14976)
__global__ void __launch_bounds__(384, 2) fused_kernel(
    const float* __restrict__ input,
    const float* __restrict__ w_om,
    const float* __restrict__ b_om,
    const float* __restrict__ bias,
    float* __restrict__ out,
    float* __restrict__ idx_out,
    float* __restrict__ mask_out)
{
    extern __shared__ float sm[];
    float*  sw   = sm;                        // [594][28]
    float*  rows = sm + 16632;                // 6 * 2 * 396
    float*  part = sm;                        // [5][27][128] (reuses sw)
    float*  omb  = sm + 21384;                // [27][128]
    float4* sWt  = (float4*)sm;               // [1152]  (phase C/D)
    int*    sPk  = (int*)(sm + 4608);         // [1152]
    float*  cols = sm + 5760;                 // [2][36*128]

    const int tid = threadIdx.x;
    const int y   = blockIdx.x;
    const int b   = blockIdx.y;
    const float inv = 1.0f / 128.0f;

    // ---- phase A: stage om weights, transposed [(c*9+t)][oc] ----
    for (int i = tid; i < CHOM * KDIM; i += 384) {
        int oc  = i / KDIM;
        int rem = i - oc * KDIM;
        sw[rem * 28 + oc] = w_om[i];
    }

    // ---- phase B: om conv, 6 groups of 11 channels, thread = 2px x 28oc ----
    const int g   = tid >> 6;      // 0..5
    const int px  = tid & 63;      // pixels px and px+64
    const int cb0 = g * 11;

    float acc[56];
#pragma unroll
    for (int j = 0; j < 27; j++) {
        float bv = (g == 0) ? b_om[j] : 0.0f;
        acc[j] = bv; acc[28 + j] = bv;
    }
    acc[27] = 0.0f; acc[55] = 0.0f;

    auto stage = [&](int c, int buf) {
        float* dst = rows + (g * 2 + buf) * 396;
        for (int s = px; s < 390; s += 64) {
            int r  = s / 130;
            int i  = s - r * 130;
            int yy = y + r - 1;
            int xx = i - 1;
            float val = 0.0f;
            if (yy >= 0 && yy < Hh && xx >= 0 && xx < Ww) {
                if (c < Cin)       val = input[(((b * Cin) + c) * Hh + yy) * Ww + xx];
                else if (c == Cin) val = yy * inv;
                else               val = xx * inv - 0.5f;
            }
            dst[r * 132 + i] = val;
        }
    };

    stage(cb0, 0);
    __syncthreads();   // sw + first rows ready

    for (int ci = 0; ci < 11; ci++) {
        asm volatile("bar.sync %0, %1;" :: "r"(g + 1), "r"(64) : "memory");
        if (ci + 1 < 11) stage(cb0 + ci + 1, (ci + 1) & 1);
        const float* rb = rows + (g * 2 + (ci & 1)) * 396;
        const float* wc = sw + (cb0 + ci) * 252;
#pragma unroll
        for (int t = 0; t < 9; t++) {
            float v0 = rb[(t / 3) * 132 + px + (t % 3)];
            float v1 = rb[(t / 3) * 132 + px + 64 + (t % 3)];
            const float4* w4 = reinterpret_cast<const float4*>(wc + t * 28);
#pragma unroll
            for (int q = 0; q < 7; q++) {
                float4 wv = w4[q];
                acc[q * 4 + 0] += v0 * wv.x; acc[28 + q * 4 + 0] += v1 * wv.x;
                acc[q * 4 + 1] += v0 * wv.y; acc[28 + q * 4 + 1] += v1 * wv.y;
                acc[q * 4 + 2] += v0 * wv.z; acc[28 + q * 4 + 2] += v1 * wv.z;
                acc[q * 4 + 3] += v0 * wv.w; acc[28 + q * 4 + 3] += v1 * wv.w;
            }
        }
    }

    __syncthreads();   // all groups done reading sw
    if (g > 0) {
        float* pb = part + (g - 1) * 3456;
#pragma unroll
        for (int j = 0; j < 27; j++) {
            pb[j * 128 + px]      = acc[j];
            pb[j * 128 + px + 64] = acc[28 + j];
        }
    }
    __syncthreads();
    if (g == 0) {
#pragma unroll
        for (int j = 0; j < 27; j++) {
            float a0 = acc[j], a1 = acc[28 + j];
#pragma unroll
            for (int i = 0; i < 5; i++) {
                a0 += part[i * 3456 + j * 128 + px];
                a1 += part[i * 3456 + j * 128 + px + 64];
            }
            if (j < 9) {
                float bse = y * inv + (float)(j / 3 - 1);
                idx_out[((b * 18 + j) * Hh + y) * Ww + px]      = bse + a0;
                idx_out[((b * 18 + j) * Hh + y) * Ww + px + 64] = bse + a1;
                omb[j * 128 + px] = a0; omb[j * 128 + px + 64] = a1;
            } else if (j < 18) {
                int j2 = j - 9;
                float c0 = (float)px * inv - 0.5f + (float)(j2 % 3 - 1);
                float c1 = (float)(px + 64) * inv - 0.5f + (float)(j2 % 3 - 1);
                idx_out[((b * 18 + j) * Hh + y) * Ww + px]      = c0 + a0;
                idx_out[((b * 18 + j) * Hh + y) * Ww + px + 64] = c1 + a1;
                omb[j * 128 + px] = a0; omb[j * 128 + px + 64] = a1;
            } else {
                float s0 = 1.0f / (1.0f + __expf(-a0));
                float s1 = 1.0f / (1.0f + __expf(-a1));
                mask_out[((b * 9 + (j - 18)) * Hh + y) * Ww + px]      = s0;
                mask_out[((b * 9 + (j - 18)) * Hh + y) * Ww + px + 64] = s1;
                omb[j * 128 + px] = s0; omb[j * 128 + px + 64] = s1;
            }
        }
    }
    __syncthreads();

    // ---- phase C: packed corner tables (overwrites sw region) ----
    for (int q = tid; q < 9 * 128; q += 384) {
        int t = q >> 7;
        int p = q & 127;
        float oh = omb[(2 * t) * 128 + p];
        float ow = omb[(2 * t + 1) * 128 + p];
        float mk = omb[(18 + t) * 128 + p];

        float ph = oh + (float)(t / 3) + (float)(y - 1);
        float pw = ow + (float)(t % 3) + (float)(p - 1);
        float h0f = floorf(ph), w0f = floorf(pw);
        float lh = ph - h0f, lw = pw - w0f;
        float hh = 1.0f - lh, hw = 1.0f - lw;
        int h0 = (int)h0f, w0 = (int)w0f;
        int h1 = h0 + 1,   w1 = w0 + 1;
        float okh0 = (h0 >= 0 && h0 < Hh) ? 1.0f : 0.0f;
        float okh1 = (h1 >= 0 && h1 < Hh) ? 1.0f : 0.0f;
        float okw0 = (w0 >= 0 && w0 < Ww) ? 1.0f : 0.0f;
        float okw1 = (w1 >= 0 && w1 < Ww) ? 1.0f : 0.0f;
        float w00 = hh * hw * okh0 * okw0 * mk;
        float w01 = hh * lw * okh0 * okw1 * mk;
        float w10 = lh * hw * okh1 * okw0 * mk;
        float w11 = lh * lw * okh1 * okw1 * mk;
        int h0c = min(max(h0, 0), Hh - 1), h1c = min(max(h1, 0), Hh - 1);
        int w0c = min(max(w0, 0), Ww - 1), w1c = min(max(w1, 0), Ww - 1);

        sWt[q] = make_float4(w00, w01, w10, w11);
        sPk[q] = (h0c * 128 + w0c) | ((h1c - h0c) << 14) | ((w1c - w0c) << 15);
    }
    __syncthreads();

    // ---- phase D ----
    const float* binp = input + b * Cin * HW;

    if (tid >= 128) {
        // producers (warps 4-11): 256 threads; 2 channels per thread per chunk
        const int ptid = tid - 128;
        const int pp   = ptid & 127;   // pixel
        const int half = ptid >> 7;    // channel half

        auto produce = [&](int cn, int buf) {
            float* dst = cols + buf * 4608 + pp;
            if (cn < 16) {
                const float* pl0 = binp + (4 * cn + half * 2) * HW;
                const float* pl1 = pl0 + HW;
                const int rbase = half * 18;
#pragma unroll
                for (int t = 0; t < 9; t++) {
                    int    pk = sPk[t * 128 + pp];
                    float4 wt = sWt[t * 128 + pp];
                    int a00 = pk & 0x3FFF;
                    int a10 = a00 + ((pk & 0x4000) >> 7);
                    int dw  = (pk >> 15) & 1;
                    int a01 = a00 + dw, a11 = a10 + dw;
                    float v0 = wt.x * pl0[a00] + wt.y * pl0[a01]
                             + wt.z * pl0[a10] + wt.w * pl0[a11];
                    float v1 = wt.x * pl1[a00] + wt.y * pl1[a01]
                             + wt.z * pl1[a10] + wt.w * pl1[a11];
                    dst[(rbase + t) * 128]     = v0;
                    dst[(rbase + 9 + t) * 128] = v1;
                }
            } else if (half == 0) {
#pragma unroll
                for (int t = 0; t < 9; t++) {
                    int    pk = sPk[t * 128 + pp];
                    float4 wt = sWt[t * 128 + pp];
                    int a00 = pk & 0x3FFF;
                    float h0c = (float)(a00 >> 7), w0c = (float)(a00 & 127);
                    float h1c = h0c + (float)((pk >> 14) & 1);
                    float w1c = w0c + (float)((pk >> 15) & 1);
                    dst[t * 128] = ((wt.x + wt.y) * h0c + (wt.z + wt.w) * h1c) * inv;
                    dst[(9 + t) * 128] =
                          (wt.x + wt.z) * (w0c * inv - 0.5f)
                        + (wt.y + wt.w) * (w1c * inv - 0.5f);
                }
            } else {
#pragma unroll
                for (int s = 18; s < 36; s++) dst[s * 128] = 0.0f;
            }
        };

        produce(0, 0);
        __syncthreads();
        for (int c = 0; c < NCHUNK; c++) {
            if (c + 1 < NCHUNK) produce(c + 1, (c + 1) & 1);
            __syncthreads();
        }
    } else {
        // consumers (warps 0-3): 16 oc x 4 px; og = warp id (uniform weight LDG)
        const int og = tid >> 5;   // 0..3 -> oc og*16 .. og*16+15
        const int pg = tid & 31;   // 0..31 -> px pg*4 .. pg*4+3
        float dacc[16][4];
#pragma unroll
        for (int i = 0; i < 16; i++)
#pragma unroll
            for (int j = 0; j < 4; j++) dacc[i][j] = 0.0f;

        __syncthreads();   // matches producer's post-produce(0) barrier
        for (int c = 0; c < NCHUNK; c++) {
            const float* cbp = cols + (c & 1) * 4608 + pg * 4;
            const float* wb  = g_wt + (c * 36) * Cout + og * 16;
#pragma unroll 4
            for (int kk = 0; kk < 36; kk++) {
                float4 cv = *reinterpret_cast<const float4*>(cbp + kk * 128);
#pragma unroll
                for (int h = 0; h < 4; h++) {
                    float4 w = __ldg(reinterpret_cast<const float4*>(
                        wb + kk * Cout + h * 4));
                    dacc[h*4+0][0] += w.x * cv.x; dacc[h*4+0][1] += w.x * cv.y;
                    dacc[h*4+0][2] += w.x * cv.z; dacc[h*4+0][3] += w.x * cv.w;
                    dacc[h*4+1][0] += w.y * cv.x; dacc[h*4+1][1] += w.y * cv.y;
                    dacc[h*4+1][2] += w.y * cv.z; dacc[h*4+1][3] += w.y * cv.w;
                    dacc[h*4+2][0] += w.z * cv.x; dacc[h*4+2][1] += w.z * cv.y;
                    dacc[h*4+2][2] += w.z * cv.z; dacc[h*4+2][3] += w.z * cv.w;
                    dacc[h*4+3][0] += w.w * cv.x; dacc[h*4+3][1] += w.w * cv.y;
                    dacc[h*4+3][2] += w.w * cv.z; dacc[h*4+3][3] += w.w * cv.w;
                }
            }
            __syncthreads();
        }

#pragma unroll
        for (int i = 0; i < 16; i++) {
            int oc = og * 16 + i;
            float bv = bias[oc];
            float4 o = make_float4(dacc[i][0] + bv, dacc[i][1] + bv,
                                   dacc[i][2] + bv, dacc[i][3] + bv);
            *reinterpret_cast<float4*>(
                out + ((b * Cout + oc) * Hh + y) * Ww + pg * 4) = o;
        }
    }
}

// ---------------- launcher ----------------
extern "C" void kernel_launch(void* const* d_in, const int* in_sizes, int n_in,
                              void* d_out, int out_size)
{
    const float* input  = (const float*)d_in[0];
    const float* weight = (const float*)d_in[1];
    const float* bias   = (const float*)d_in[2];
    const float* w_om   = (const float*)d_in[3];
    const float* b_om   = (const float*)d_in[4];

    float* out      = (float*)d_out;
    float* idx_out  = out + (size_t)Bn * Cout * Hh * Ww;
    float* mask_out = idx_out + (size_t)Bn * 18 * Hh * Ww;

    const int smF = 24840 * 4;   // 99,360 B
    cudaFuncSetAttribute(fused_kernel, cudaFuncAttributeMaxDynamicSharedMemorySize, smF);

    prep_wt_kernel<<<(KPAD * Cout + 255) / 256, 256>>>(weight);
    fused_kernel<<<dim3(Hh, Bn), 384, smF>>>(input, w_om, b_om, bias,
                                             out, idx_out, mask_out);
}

// round 11
// speedup vs baseline: 3.5823x; 3.5823x over previous
#include <cuda_runtime.h>

#define Bn   8
#define Cin  64
#define Hh   128
#define Ww   128
#define HW   (Hh*Ww)
#define Cout 64
#define CIN2 66
#define KDIM 594    // CIN2 * 9
#define CHOM 27
#define NCHUNK 17   // 16 chunks x 4 ch + 1 chunk (coord ch 64,65 + pad)
#define KPAD 612    // 17 * 36

// ---------------- scratch ----------------
__device__ float g_wt[KPAD*Cout];   // transposed main weight [k][o], zero-padded

__global__ void prep_wt_kernel(const float* __restrict__ w)
{
    int i = blockIdx.x * 256 + threadIdx.x;
    if (i < KPAD * Cout) {
        int k = i >> 6;
        int o = i & 63;
        g_wt[i] = (k < KDIM) ? w[o * KDIM + k] : 0.0f;
    }
}

// ---------------- fused kernel ----------------
// One block per (row y, batch b); 384 threads.
// Phase B: om conv, 6 c-groups (11 ch) x 64 threads; thread = 2 px x 28 oc.
// Phase C: packed corner tables (sWt float4 + sPk packed b32).
// Phase D: producers = warps 8-11 (128 thr, 4ch per chunk per thread),
//          consumers = warps 0-7 (8oc x 4px each, og = warp id).
// Smem floats: B: sw[0,16632) rows[16632,21384) omb[21384,24840)
//              C/D: sWt[0,4608) sPk[4608,5760) cols[5760,14976)
__global__ void __launch_bounds__(384, 2) fused_kernel(
    const float* __restrict__ input,
    const float* __restrict__ w_om,
    const float* __restrict__ b_om,
    const float* __restrict__ bias,
    float* __restrict__ out,
    float* __restrict__ idx_out,
    float* __restrict__ mask_out)
{
    extern __shared__ float sm[];
    float*  sw   = sm;                        // [594][28]
    float*  rows = sm + 16632;                // 6 * 2 * 396
    float*  part = sm;                        // [5][27][128] (reuses sw)
    float*  omb  = sm + 21384;                // [27][128]
    float4* sWt  = (float4*)sm;               // [1152]  (phase C/D)
    int*    sPk  = (int*)(sm + 4608);         // [1152]
    float*  cols = sm + 5760;                 // [2][36*128]

    const int tid = threadIdx.x;
    const int y   = blockIdx.x;
    const int b   = blockIdx.y;
    const float inv = 1.0f / 128.0f;

    // ---- phase A: stage om weights, transposed [(c*9+t)][oc] ----
    for (int i = tid; i < CHOM * KDIM; i += 384) {
        int oc  = i / KDIM;
        int rem = i - oc * KDIM;
        sw[rem * 28 + oc] = w_om[i];
    }

    // ---- phase B: om conv, 6 groups of 11 channels, thread = 2px x 28oc ----
    const int g   = tid >> 6;      // 0..5
    const int px  = tid & 63;      // pixels px and px+64
    const int cb0 = g * 11;

    float acc[56];
#pragma unroll
    for (int j = 0; j < 27; j++) {
        float bv = (g == 0) ? b_om[j] : 0.0f;
        acc[j] = bv; acc[28 + j] = bv;
    }
    acc[27] = 0.0f; acc[55] = 0.0f;

    auto stage = [&](int c, int buf) {
        float* dst = rows + (g * 2 + buf) * 396;
        for (int s = px; s < 390; s += 64) {
            int r  = s / 130;
            int i  = s - r * 130;
            int yy = y + r - 1;
            int xx = i - 1;
            float val = 0.0f;
            if (yy >= 0 && yy < Hh && xx >= 0 && xx < Ww) {
                if (c < Cin)       val = input[(((b * Cin) + c) * Hh + yy) * Ww + xx];
                else if (c == Cin) val = yy * inv;
                else               val = xx * inv - 0.5f;
            }
            dst[r * 132 + i] = val;
        }
    };

    stage(cb0, 0);
    __syncthreads();   // sw + first rows ready

    for (int ci = 0; ci < 11; ci++) {
        asm volatile("bar.sync %0, %1;" :: "r"(g + 1), "r"(64) : "memory");
        if (ci + 1 < 11) stage(cb0 + ci + 1, (ci + 1) & 1);
        const float* rb = rows + (g * 2 + (ci & 1)) * 396;
        const float* wc = sw + (cb0 + ci) * 252;
#pragma unroll
        for (int t = 0; t < 9; t++) {
            float v0 = rb[(t / 3) * 132 + px + (t % 3)];
            float v1 = rb[(t / 3) * 132 + px + 64 + (t % 3)];
            const float4* w4 = reinterpret_cast<const float4*>(wc + t * 28);
#pragma unroll
            for (int q = 0; q < 7; q++) {
                float4 wv = w4[q];
                acc[q * 4 + 0] += v0 * wv.x; acc[28 + q * 4 + 0] += v1 * wv.x;
                acc[q * 4 + 1] += v0 * wv.y; acc[28 + q * 4 + 1] += v1 * wv.y;
                acc[q * 4 + 2] += v0 * wv.z; acc[28 + q * 4 + 2] += v1 * wv.z;
                acc[q * 4 + 3] += v0 * wv.w; acc[28 + q * 4 + 3] += v1 * wv.w;
            }
        }
    }

    __syncthreads();   // all groups done reading sw
    if (g > 0) {
        float* pb = part + (g - 1) * 3456;
#pragma unroll
        for (int j = 0; j < 27; j++) {
            pb[j * 128 + px]      = acc[j];
            pb[j * 128 + px + 64] = acc[28 + j];
        }
    }
    __syncthreads();
    if (g == 0) {
#pragma unroll
        for (int j = 0; j < 27; j++) {
            float a0 = acc[j], a1 = acc[28 + j];
#pragma unroll
            for (int i = 0; i < 5; i++) {
                a0 += part[i * 3456 + j * 128 + px];
                a1 += part[i * 3456 + j * 128 + px + 64];
            }
            if (j < 9) {
                float bse = y * inv + (float)(j / 3 - 1);
                idx_out[((b * 18 + j) * Hh + y) * Ww + px]      = bse + a0;
                idx_out[((b * 18 + j) * Hh + y) * Ww + px + 64] = bse + a1;
                omb[j * 128 + px] = a0; omb[j * 128 + px + 64] = a1;
            } else if (j < 18) {
                int j2 = j - 9;
                float c0 = (float)px * inv - 0.5f + (float)(j2 % 3 - 1);
                float c1 = (float)(px + 64) * inv - 0.5f + (float)(j2 % 3 - 1);
                idx_out[((b * 18 + j) * Hh + y) * Ww + px]      = c0 + a0;
                idx_out[((b * 18 + j) * Hh + y) * Ww + px + 64] = c1 + a1;
                omb[j * 128 + px] = a0; omb[j * 128 + px + 64] = a1;
            } else {
                float s0 = 1.0f / (1.0f + __expf(-a0));
                float s1 = 1.0f / (1.0f + __expf(-a1));
                mask_out[((b * 9 + (j - 18)) * Hh + y) * Ww + px]      = s0;
                mask_out[((b * 9 + (j - 18)) * Hh + y) * Ww + px + 64] = s1;
                omb[j * 128 + px] = s0; omb[j * 128 + px + 64] = s1;
            }
        }
    }
    __syncthreads();

    // ---- phase C: packed corner tables (overwrites sw region) ----
    for (int q = tid; q < 9 * 128; q += 384) {
        int t = q >> 7;
        int p = q & 127;
        float oh = omb[(2 * t) * 128 + p];
        float ow = omb[(2 * t + 1) * 128 + p];
        float mk = omb[(18 + t) * 128 + p];

        float ph = oh + (float)(t / 3) + (float)(y - 1);
        float pw = ow + (float)(t % 3) + (float)(p - 1);
        float h0f = floorf(ph), w0f = floorf(pw);
        float lh = ph - h0f, lw = pw - w0f;
        float hh = 1.0f - lh, hw = 1.0f - lw;
        int h0 = (int)h0f, w0 = (int)w0f;
        int h1 = h0 + 1,   w1 = w0 + 1;
        float okh0 = (h0 >= 0 && h0 < Hh) ? 1.0f : 0.0f;
        float okh1 = (h1 >= 0 && h1 < Hh) ? 1.0f : 0.0f;
        float okw0 = (w0 >= 0 && w0 < Ww) ? 1.0f : 0.0f;
        float okw1 = (w1 >= 0 && w1 < Ww) ? 1.0f : 0.0f;
        float w00 = hh * hw * okh0 * okw0 * mk;
        float w01 = hh * lw * okh0 * okw1 * mk;
        float w10 = lh * hw * okh1 * okw0 * mk;
        float w11 = lh * lw * okh1 * okw1 * mk;
        int h0c = min(max(h0, 0), Hh - 1), h1c = min(max(h1, 0), Hh - 1);
        int w0c = min(max(w0, 0), Ww - 1), w1c = min(max(w1, 0), Ww - 1);

        sWt[q] = make_float4(w00, w01, w10, w11);
        sPk[q] = (h0c * 128 + w0c) | ((h1c - h0c) << 14) | ((w1c - w0c) << 15);
    }
    __syncthreads();

    // ---- phase D: warp-specialized gather + GEMM (4-channel chunks) ----
    const float* binp = input + b * Cin * HW;

    if (tid >= 256) {
        // producers (warps 8-11): one pixel per thread, 4 channels per chunk
        const int ptid = tid - 256;

        auto produce = [&](int cn, int buf) {
            float* dst = cols + buf * 4608 + ptid;
            if (cn < 16) {
                const float* pl0 = binp + (4 * cn) * HW;
#pragma unroll
                for (int t = 0; t < 9; t++) {
                    int    pk = sPk[t * 128 + ptid];
                    float4 wt = sWt[t * 128 + ptid];
                    int a00 = pk & 0x3FFF;
                    int a10 = a00 + ((pk & 0x4000) >> 7);   // +128 if dh
                    int dw  = (pk >> 15) & 1;
                    int a01 = a00 + dw, a11 = a10 + dw;
                    const float* pl = pl0;
#pragma unroll
                    for (int cc = 0; cc < 4; cc++, pl += HW) {
                        float v = wt.x * pl[a00] + wt.y * pl[a01]
                                + wt.z * pl[a10] + wt.w * pl[a11];
                        dst[(cc * 9 + t) * 128] = v;
                    }
                }
            } else {
#pragma unroll
                for (int t = 0; t < 9; t++) {
                    int    pk = sPk[t * 128 + ptid];
                    float4 wt = sWt[t * 128 + ptid];
                    int a00 = pk & 0x3FFF;
                    float h0c = (float)(a00 >> 7), w0c = (float)(a00 & 127);
                    float h1c = h0c + (float)((pk >> 14) & 1);
                    float w1c = w0c + (float)((pk >> 15) & 1);
                    dst[t * 128] = ((wt.x + wt.y) * h0c + (wt.z + wt.w) * h1c) * inv;
                    dst[(9 + t) * 128] =
                          (wt.x + wt.z) * (w0c * inv - 0.5f)
                        + (wt.y + wt.w) * (w1c * inv - 0.5f);
                }
#pragma unroll
                for (int s = 18; s < 36; s++) dst[s * 128] = 0.0f;
            }
        };

        produce(0, 0);
        __syncthreads();
        for (int c = 0; c < NCHUNK; c++) {
            if (c + 1 < NCHUNK) produce(c + 1, (c + 1) & 1);
            __syncthreads();
        }
    } else {
        // consumers (warps 0-7): 8 oc x 4 px; og = warp id (uniform weight LDG)
        const int og = tid >> 5;
        const int pg = tid & 31;
        float dacc[8][4];
#pragma unroll
        for (int i = 0; i < 8; i++)
#pragma unroll
            for (int j = 0; j < 4; j++) dacc[i][j] = 0.0f;

        __syncthreads();   // matches producer's post-produce(0) barrier
        for (int c = 0; c < NCHUNK; c++) {
            const float* cbp = cols + (c & 1) * 4608 + pg * 4;
            const float* wb  = g_wt + (c * 36) * Cout + og * 8;
#pragma unroll 6
            for (int kk = 0; kk < 36; kk++) {
                float4 w0 = __ldg(reinterpret_cast<const float4*>(wb + kk * Cout));
                float4 w1 = __ldg(reinterpret_cast<const float4*>(wb + kk * Cout + 4));
                float4 cv = *reinterpret_cast<const float4*>(cbp + kk * 128);
                dacc[0][0] += w0.x * cv.x; dacc[0][1] += w0.x * cv.y;
                dacc[0][2] += w0.x * cv.z; dacc[0][3] += w0.x * cv.w;
                dacc[1][0] += w0.y * cv.x; dacc[1][1] += w0.y * cv.y;
                dacc[1][2] += w0.y * cv.z; dacc[1][3] += w0.y * cv.w;
                dacc[2][0] += w0.z * cv.x; dacc[2][1] += w0.z * cv.y;
                dacc[2][2] += w0.z * cv.z; dacc[2][3] += w0.z * cv.w;
                dacc[3][0] += w0.w * cv.x; dacc[3][1] += w0.w * cv.y;
                dacc[3][2] += w0.w * cv.z; dacc[3][3] += w0.w * cv.w;
                dacc[4][0] += w1.x * cv.x; dacc[4][1] += w1.x * cv.y;
                dacc[4][2] += w1.x * cv.z; dacc[4][3] += w1.x * cv.w;
                dacc[5][0] += w1.y * cv.x; dacc[5][1] += w1.y * cv.y;
                dacc[5][2] += w1.y * cv.z; dacc[5][3] += w1.y * cv.w;
                dacc[6][0] += w1.z * cv.x; dacc[6][1] += w1.z * cv.y;
                dacc[6][2] += w1.z * cv.z; dacc[6][3] += w1.z * cv.w;
                dacc[7][0] += w1.w * cv.x; dacc[7][1] += w1.w * cv.y;
                dacc[7][2] += w1.w * cv.z; dacc[7][3] += w1.w * cv.w;
            }
            __syncthreads();
        }

#pragma unroll
        for (int i = 0; i < 8; i++) {
            int oc = og * 8 + i;
            float bv = bias[oc];
            float4 o = make_float4(dacc[i][0] + bv, dacc[i][1] + bv,
                                   dacc[i][2] + bv, dacc[i][3] + bv);
            *reinterpret_cast<float4*>(
                out + ((b * Cout + oc) * Hh + y) * Ww + pg * 4) = o;
        }
    }
}

// ---------------- launcher ----------------
extern "C" void kernel_launch(void* const* d_in, const int* in_sizes, int n_in,
                              void* d_out, int out_size)
{
    const float* input  = (const float*)d_in[0];
    const float* weight = (const float*)d_in[1];
    const float* bias   = (const float*)d_in[2];
    const float* w_om   = (const float*)d_in[3];
    const float* b_om   = (const float*)d_in[4];

    float* out      = (float*)d_out;
    float* idx_out  = out + (size_t)Bn * Cout * Hh * Ww;
    float* mask_out = idx_out + (size_t)Bn * 18 * Hh * Ww;

    const int smF = 24840 * 4;   // 99,360 B
    cudaFuncSetAttribute(fused_kernel, cudaFuncAttributeMaxDynamicSharedMemorySize, smF);

    prep_wt_kernel<<<(KPAD * Cout + 255) / 256, 256>>>(weight);
    fused_kernel<<<dim3(Hh, Bn), 384, smF>>>(input, w_om, b_om, bias,
                                             out, idx_out, mask_out);
}

// round 12
// speedup vs baseline: 3.6728x; 1.0253x over previous
#include <cuda_runtime.h>
#include <cuda_fp16.h>

#define Bn   8
#define Cin  64
#define Hh   128
#define Ww   128
#define HW   (Hh*Ww)
#define Cout 64
#define CIN2 66
#define KDIM 594    // CIN2 * 9
#define CHOM 27
#define NCHUNK 17   // 16 chunks x 4 ch + 1 chunk (coord ch 64,65 + pad)
#define KPAD 612    // 17 * 36

// ---------------- scratch ----------------
__device__ float g_wt[KPAD*Cout];   // transposed main weight [k][o], zero-padded

__global__ void prep_wt_kernel(const float* __restrict__ w)
{
    int i = blockIdx.x * 256 + threadIdx.x;
    if (i < KPAD * Cout) {
        int k = i >> 6;
        int o = i & 63;
        g_wt[i] = (k < KDIM) ? w[o * KDIM + k] : 0.0f;
    }
}

// ---------------- fused kernel ----------------
// One block per (row y, batch b); 384 threads.
// Phase B: om conv, 6 c-groups (11 ch) x 64 threads; thread = 2 px x 28 oc.
// Phase C: packed corner tables (sWt float4 + sPk packed b32).
// Phase D: producers = warps 8-11 (128 thr, 4ch/chunk, fp16 STS),
//          consumers = warps 0-7 (8oc x 4px, fp16 cols loads, fp32 FMA).
// Smem floats: B: sw[0,16632) rows[16632,21384) omb[21384,24840)
//              C/D: sWt[0,4608) sPk[4608,5760) cols16[5760..10368) (half)
__global__ void __launch_bounds__(384, 2) fused_kernel(
    const float* __restrict__ input,
    const float* __restrict__ w_om,
    const float* __restrict__ b_om,
    const float* __restrict__ bias,
    float* __restrict__ out,
    float* __restrict__ idx_out,
    float* __restrict__ mask_out)
{
    extern __shared__ float sm[];
    float*  sw   = sm;                        // [594][28]
    float*  rows = sm + 16632;                // 6 * 2 * 396
    float*  part = sm;                        // [5][27][128] (reuses sw)
    float*  omb  = sm + 21384;                // [27][128]
    float4* sWt  = (float4*)sm;               // [1152]  (phase C/D)
    int*    sPk  = (int*)(sm + 4608);         // [1152]
    __half* cols = (__half*)(sm + 5760);      // [2][36*128] halves

    const int tid = threadIdx.x;
    const int y   = blockIdx.x;
    const int b   = blockIdx.y;
    const float inv = 1.0f / 128.0f;

    // ---- phase A: stage om weights, transposed [(c*9+t)][oc] ----
    for (int i = tid; i < CHOM * KDIM; i += 384) {
        int oc  = i / KDIM;
        int rem = i - oc * KDIM;
        sw[rem * 28 + oc] = w_om[i];
    }

    // ---- phase B: om conv, 6 groups of 11 channels, thread = 2px x 28oc ----
    const int g   = tid >> 6;      // 0..5
    const int px  = tid & 63;      // pixels px and px+64
    const int cb0 = g * 11;

    float acc[56];
#pragma unroll
    for (int j = 0; j < 27; j++) {
        float bv = (g == 0) ? b_om[j] : 0.0f;
        acc[j] = bv; acc[28 + j] = bv;
    }
    acc[27] = 0.0f; acc[55] = 0.0f;

    auto stage = [&](int c, int buf) {
        float* dst = rows + (g * 2 + buf) * 396;
        for (int s = px; s < 390; s += 64) {
            int r  = s / 130;
            int i  = s - r * 130;
            int yy = y + r - 1;
            int xx = i - 1;
            float val = 0.0f;
            if (yy >= 0 && yy < Hh && xx >= 0 && xx < Ww) {
                if (c < Cin)       val = input[(((b * Cin) + c) * Hh + yy) * Ww + xx];
                else if (c == Cin) val = yy * inv;
                else               val = xx * inv - 0.5f;
            }
            dst[r * 132 + i] = val;
        }
    };

    stage(cb0, 0);
    __syncthreads();   // sw + first rows ready

    for (int ci = 0; ci < 11; ci++) {
        asm volatile("bar.sync %0, %1;" :: "r"(g + 1), "r"(64) : "memory");
        if (ci + 1 < 11) stage(cb0 + ci + 1, (ci + 1) & 1);
        const float* rb = rows + (g * 2 + (ci & 1)) * 396;
        const float* wc = sw + (cb0 + ci) * 252;
#pragma unroll
        for (int t = 0; t < 9; t++) {
            float v0 = rb[(t / 3) * 132 + px + (t % 3)];
            float v1 = rb[(t / 3) * 132 + px + 64 + (t % 3)];
            const float4* w4 = reinterpret_cast<const float4*>(wc + t * 28);
#pragma unroll
            for (int q = 0; q < 7; q++) {
                float4 wv = w4[q];
                acc[q * 4 + 0] += v0 * wv.x; acc[28 + q * 4 + 0] += v1 * wv.x;
                acc[q * 4 + 1] += v0 * wv.y; acc[28 + q * 4 + 1] += v1 * wv.y;
                acc[q * 4 + 2] += v0 * wv.z; acc[28 + q * 4 + 2] += v1 * wv.z;
                acc[q * 4 + 3] += v0 * wv.w; acc[28 + q * 4 + 3] += v1 * wv.w;
            }
        }
    }

    __syncthreads();   // all groups done reading sw
    if (g > 0) {
        float* pb = part + (g - 1) * 3456;
#pragma unroll
        for (int j = 0; j < 27; j++) {
            pb[j * 128 + px]      = acc[j];
            pb[j * 128 + px + 64] = acc[28 + j];
        }
    }
    __syncthreads();
    if (g == 0) {
#pragma unroll
        for (int j = 0; j < 27; j++) {
            float a0 = acc[j], a1 = acc[28 + j];
#pragma unroll
            for (int i = 0; i < 5; i++) {
                a0 += part[i * 3456 + j * 128 + px];
                a1 += part[i * 3456 + j * 128 + px + 64];
            }
            if (j < 9) {
                float bse = y * inv + (float)(j / 3 - 1);
                idx_out[((b * 18 + j) * Hh + y) * Ww + px]      = bse + a0;
                idx_out[((b * 18 + j) * Hh + y) * Ww + px + 64] = bse + a1;
                omb[j * 128 + px] = a0; omb[j * 128 + px + 64] = a1;
            } else if (j < 18) {
                int j2 = j - 9;
                float c0 = (float)px * inv - 0.5f + (float)(j2 % 3 - 1);
                float c1 = (float)(px + 64) * inv - 0.5f + (float)(j2 % 3 - 1);
                idx_out[((b * 18 + j) * Hh + y) * Ww + px]      = c0 + a0;
                idx_out[((b * 18 + j) * Hh + y) * Ww + px + 64] = c1 + a1;
                omb[j * 128 + px] = a0; omb[j * 128 + px + 64] = a1;
            } else {
                float s0 = 1.0f / (1.0f + __expf(-a0));
                float s1 = 1.0f / (1.0f + __expf(-a1));
                mask_out[((b * 9 + (j - 18)) * Hh + y) * Ww + px]      = s0;
                mask_out[((b * 9 + (j - 18)) * Hh + y) * Ww + px + 64] = s1;
                omb[j * 128 + px] = s0; omb[j * 128 + px + 64] = s1;
            }
        }
    }
    __syncthreads();

    // ---- phase C: packed corner tables (overwrites sw region) ----
    for (int q = tid; q < 9 * 128; q += 384) {
        int t = q >> 7;
        int p = q & 127;
        float oh = omb[(2 * t) * 128 + p];
        float ow = omb[(2 * t + 1) * 128 + p];
        float mk = omb[(18 + t) * 128 + p];

        float ph = oh + (float)(t / 3) + (float)(y - 1);
        float pw = ow + (float)(t % 3) + (float)(p - 1);
        float h0f = floorf(ph), w0f = floorf(pw);
        float lh = ph - h0f, lw = pw - w0f;
        float hh = 1.0f - lh, hw = 1.0f - lw;
        int h0 = (int)h0f, w0 = (int)w0f;
        int h1 = h0 + 1,   w1 = w0 + 1;
        float okh0 = (h0 >= 0 && h0 < Hh) ? 1.0f : 0.0f;
        float okh1 = (h1 >= 0 && h1 < Hh) ? 1.0f : 0.0f;
        float okw0 = (w0 >= 0 && w0 < Ww) ? 1.0f : 0.0f;
        float okw1 = (w1 >= 0 && w1 < Ww) ? 1.0f : 0.0f;
        float w00 = hh * hw * okh0 * okw0 * mk;
        float w01 = hh * lw * okh0 * okw1 * mk;
        float w10 = lh * hw * okh1 * okw0 * mk;
        float w11 = lh * lw * okh1 * okw1 * mk;
        int h0c = min(max(h0, 0), Hh - 1), h1c = min(max(h1, 0), Hh - 1);
        int w0c = min(max(w0, 0), Ww - 1), w1c = min(max(w1, 0), Ww - 1);

        sWt[q] = make_float4(w00, w01, w10, w11);
        sPk[q] = (h0c * 128 + w0c) | ((h1c - h0c) << 14) | ((w1c - w0c) << 15);
    }
    __syncthreads();

    // ---- phase D: warp-specialized gather + GEMM (4-channel chunks, fp16 cols) ----
    const float* binp = input + b * Cin * HW;

    if (tid >= 256) {
        // producers (warps 8-11): one pixel per thread, 4 channels per chunk
        const int ptid = tid - 256;

        auto produce = [&](int cn, int buf) {
            __half* dst = cols + buf * 4608 + ptid;
            if (cn < 16) {
                const float* pl0 = binp + (4 * cn) * HW;
#pragma unroll
                for (int t = 0; t < 9; t++) {
                    int    pk = sPk[t * 128 + ptid];
                    float4 wt = sWt[t * 128 + ptid];
                    int a00 = pk & 0x3FFF;
                    int a10 = a00 + ((pk & 0x4000) >> 7);   // +128 if dh
                    int dw  = (pk >> 15) & 1;
                    int a01 = a00 + dw, a11 = a10 + dw;
                    const float* pl = pl0;
#pragma unroll
                    for (int cc = 0; cc < 4; cc++, pl += HW) {
                        float v = wt.x * pl[a00] + wt.y * pl[a01]
                                + wt.z * pl[a10] + wt.w * pl[a11];
                        dst[(cc * 9 + t) * 128] = __float2half_rn(v);
                    }
                }
            } else {
#pragma unroll
                for (int t = 0; t < 9; t++) {
                    int    pk = sPk[t * 128 + ptid];
                    float4 wt = sWt[t * 128 + ptid];
                    int a00 = pk & 0x3FFF;
                    float h0c = (float)(a00 >> 7), w0c = (float)(a00 & 127);
                    float h1c = h0c + (float)((pk >> 14) & 1);
                    float w1c = w0c + (float)((pk >> 15) & 1);
                    dst[t * 128] = __float2half_rn(
                        ((wt.x + wt.y) * h0c + (wt.z + wt.w) * h1c) * inv);
                    dst[(9 + t) * 128] = __float2half_rn(
                          (wt.x + wt.z) * (w0c * inv - 0.5f)
                        + (wt.y + wt.w) * (w1c * inv - 0.5f));
                }
#pragma unroll
                for (int s = 18; s < 36; s++) dst[s * 128] = __half(0.0f);
            }
        };

        produce(0, 0);
        __syncthreads();
        for (int c = 0; c < NCHUNK; c++) {
            if (c + 1 < NCHUNK) produce(c + 1, (c + 1) & 1);
            __syncthreads();
        }
    } else {
        // consumers (warps 0-7): 8 oc x 4 px; og = warp id (uniform weight LDG)
        const int og = tid >> 5;
        const int pg = tid & 31;
        float dacc[8][4];
#pragma unroll
        for (int i = 0; i < 8; i++)
#pragma unroll
            for (int j = 0; j < 4; j++) dacc[i][j] = 0.0f;

        __syncthreads();   // matches producer's post-produce(0) barrier
        for (int c = 0; c < NCHUNK; c++) {
            const __half* cbp = cols + (c & 1) * 4608 + pg * 4;
            const float*  wb  = g_wt + (c * 36) * Cout + og * 8;
#pragma unroll 6
            for (int kk = 0; kk < 36; kk++) {
                float4 w0 = __ldg(reinterpret_cast<const float4*>(wb + kk * Cout));
                float4 w1 = __ldg(reinterpret_cast<const float4*>(wb + kk * Cout + 4));
                uint2  u  = *reinterpret_cast<const uint2*>(cbp + kk * 128);
                float2 lo = __half22float2(*reinterpret_cast<__half2*>(&u.x));
                float2 hi = __half22float2(*reinterpret_cast<__half2*>(&u.y));
                float4 cv = make_float4(lo.x, lo.y, hi.x, hi.y);
                dacc[0][0] += w0.x * cv.x; dacc[0][1] += w0.x * cv.y;
                dacc[0][2] += w0.x * cv.z; dacc[0][3] += w0.x * cv.w;
                dacc[1][0] += w0.y * cv.x; dacc[1][1] += w0.y * cv.y;
                dacc[1][2] += w0.y * cv.z; dacc[1][3] += w0.y * cv.w;
                dacc[2][0] += w0.z * cv.x; dacc[2][1] += w0.z * cv.y;
                dacc[2][2] += w0.z * cv.z; dacc[2][3] += w0.z * cv.w;
                dacc[3][0] += w0.w * cv.x; dacc[3][1] += w0.w * cv.y;
                dacc[3][2] += w0.w * cv.z; dacc[3][3] += w0.w * cv.w;
                dacc[4][0] += w1.x * cv.x; dacc[4][1] += w1.x * cv.y;
                dacc[4][2] += w1.x * cv.z; dacc[4][3] += w1.x * cv.w;
                dacc[5][0] += w1.y * cv.x; dacc[5][1] += w1.y * cv.y;
                dacc[5][2] += w1.y * cv.z; dacc[5][3] += w1.y * cv.w;
                dacc[6][0] += w1.z * cv.x; dacc[6][1] += w1.z * cv.y;
                dacc[6][2] += w1.z * cv.z; dacc[6][3] += w1.z * cv.w;
                dacc[7][0] += w1.w * cv.x; dacc[7][1] += w1.w * cv.y;
                dacc[7][2] += w1.w * cv.z; dacc[7][3] += w1.w * cv.w;
            }
            __syncthreads();
        }

#pragma unroll
        for (int i = 0; i < 8; i++) {
            int oc = og * 8 + i;
            float bv = bias[oc];
            float4 o = make_float4(dacc[i][0] + bv, dacc[i][1] + bv,
                                   dacc[i][2] + bv, dacc[i][3] + bv);
            *reinterpret_cast<float4*>(
                out + ((b * Cout + oc) * Hh + y) * Ww + pg * 4) = o;
        }
    }
}

// ---------------- launcher ----------------
extern "C" void kernel_launch(void* const* d_in, const int* in_sizes, int n_in,
                              void* d_out, int out_size)
{
    const float* input  = (const float*)d_in[0];
    const float* weight = (const float*)d_in[1];
    const float* bias   = (const float*)d_in[2];
    const float* w_om   = (const float*)d_in[3];
    const float* b_om   = (const float*)d_in[4];

    float* out      = (float*)d_out;
    float* idx_out  = out + (size_t)Bn * Cout * Hh * Ww;
    float* mask_out = idx_out + (size_t)Bn * 18 * Hh * Ww;

    const int smF = 24840 * 4;   // 99,360 B
    cudaFuncSetAttribute(fused_kernel, cudaFuncAttributeMaxDynamicSharedMemorySize, smF);

    prep_wt_kernel<<<(KPAD * Cout + 255) / 256, 256>>>(weight);
    fused_kernel<<<dim3(Hh, Bn), 384, smF>>>(input, w_om, b_om, bias,
                                             out, idx_out, mask_out);
}

// round 13
// speedup vs baseline: 5.6586x; 1.5407x over previous
#include <cuda_runtime.h>
#include <cuda_fp16.h>
#include <cstdint>

#define Bn   8
#define Cin  64
#define Hh   128
#define Ww   128
#define HW   (Hh*Ww)
#define Cout 64
#define CIN2 66
#define KDIM 594    // CIN2 * 9
#define CHOM 27
#define NCH  5      // 4 chunks x 144 k (16 ch) + 1 tail chunk (64 k: coords+pad)
#define RS   136    // cols row stride in halves (272 B -> conflict-free ldmatrix)
#define BUFH (144*RS)
#define NKSTEP 40   // 640 / 16

// ---------------- scratch ----------------
// B fragments for mma.m16n8k16: [kstep][nfrag][lane] -> uint2 (4 halves)
__device__ uint2 g_wfrag[NKSTEP*8*32];

__global__ void prep_wfrag_kernel(const float* __restrict__ w)
{
    int i = blockIdx.x * 256 + threadIdx.x;
    if (i >= NKSTEP * 256) return;
    int kstep = i >> 8;
    int rem   = i & 255;
    int nfrag = rem >> 5;
    int lane  = rem & 31;
    int n  = nfrag * 8 + (lane >> 2);
    int kb = kstep * 16 + (lane & 3) * 2;
    auto B = [&](int k) -> __half {
        return __float2half_rn((k < KDIM) ? w[n * KDIM + k] : 0.0f);
    };
    uint32_t x = (uint32_t)__half_as_ushort(B(kb))
               | ((uint32_t)__half_as_ushort(B(kb + 1)) << 16);
    uint32_t yv = (uint32_t)__half_as_ushort(B(kb + 8))
                | ((uint32_t)__half_as_ushort(B(kb + 9)) << 16);
    g_wfrag[i] = make_uint2(x, yv);
}

__device__ __forceinline__ uint32_t smem_u32(const void* p) {
    uint32_t a;
    asm("{ .reg .u64 t; cvta.to.shared.u64 t, %1; cvt.u32.u64 %0, t; }"
        : "=r"(a) : "l"(p));
    return a;
}

// ---------------- fused kernel ----------------
// One block per (row y, batch b); 384 threads.
// Phase B: om conv (6 c-groups x 64 thr, 2px x 28oc each). Phase C: packed
// corner tables. Phase D: producers = warps 8-11 (128 thr, 16 ch/chunk),
// consumers = warps 0-7: mma.sync m16n8k16, each warp 16px x 64oc.
// Smem floats: B: sw[0,16632) rows[16632,21384) omb[21384,24840)
//              C/D: sWt[0,4608) sPk[4608,5760) cols fp16 [5760 .. +78336B)
__global__ void __launch_bounds__(384, 2) fused_kernel(
    const float* __restrict__ input,
    const float* __restrict__ w_om,
    const float* __restrict__ b_om,
    const float* __restrict__ bias,
    float* __restrict__ out,
    float* __restrict__ idx_out,
    float* __restrict__ mask_out)
{
    extern __shared__ float sm[];
    float*  sw   = sm;                        // [594][28]
    float*  rows = sm + 16632;                // 6 * 2 * 396
    float*  part = sm;                        // [5][27][128] (reuses sw)
    float*  omb  = sm + 21384;                // [27][128]
    float4* sWt  = (float4*)sm;               // [1152]  (phase C/D)
    int*    sPk  = (int*)(sm + 4608);         // [1152]
    __half* cols = (__half*)(sm + 5760);      // [2][144][136] halves

    const int tid = threadIdx.x;
    const int y   = blockIdx.x;
    const int b   = blockIdx.y;
    const float inv = 1.0f / 128.0f;

    // ---- phase A: stage om weights, transposed [(c*9+t)][oc] ----
    for (int i = tid; i < CHOM * KDIM; i += 384) {
        int oc  = i / KDIM;
        int rem = i - oc * KDIM;
        sw[rem * 28 + oc] = w_om[i];
    }

    // ---- phase B: om conv, 6 groups of 11 channels, thread = 2px x 28oc ----
    const int g   = tid >> 6;      // 0..5
    const int px  = tid & 63;      // pixels px and px+64
    const int cb0 = g * 11;

    float acc[56];
#pragma unroll
    for (int j = 0; j < 27; j++) {
        float bv = (g == 0) ? b_om[j] : 0.0f;
        acc[j] = bv; acc[28 + j] = bv;
    }
    acc[27] = 0.0f; acc[55] = 0.0f;

    auto stage = [&](int c, int buf) {
        float* dst = rows + (g * 2 + buf) * 396;
        for (int s = px; s < 390; s += 64) {
            int r  = s / 130;
            int i  = s - r * 130;
            int yy = y + r - 1;
            int xx = i - 1;
            float val = 0.0f;
            if (yy >= 0 && yy < Hh && xx >= 0 && xx < Ww) {
                if (c < Cin)       val = input[(((b * Cin) + c) * Hh + yy) * Ww + xx];
                else if (c == Cin) val = yy * inv;
                else               val = xx * inv - 0.5f;
            }
            dst[r * 132 + i] = val;
        }
    };

    stage(cb0, 0);
    __syncthreads();   // sw + first rows ready

    for (int ci = 0; ci < 11; ci++) {
        asm volatile("bar.sync %0, %1;" :: "r"(g + 1), "r"(64) : "memory");
        if (ci + 1 < 11) stage(cb0 + ci + 1, (ci + 1) & 1);
        const float* rb = rows + (g * 2 + (ci & 1)) * 396;
        const float* wc = sw + (cb0 + ci) * 252;
#pragma unroll
        for (int t = 0; t < 9; t++) {
            float v0 = rb[(t / 3) * 132 + px + (t % 3)];
            float v1 = rb[(t / 3) * 132 + px + 64 + (t % 3)];
            const float4* w4 = reinterpret_cast<const float4*>(wc + t * 28);
#pragma unroll
            for (int q = 0; q < 7; q++) {
                float4 wv = w4[q];
                acc[q * 4 + 0] += v0 * wv.x; acc[28 + q * 4 + 0] += v1 * wv.x;
                acc[q * 4 + 1] += v0 * wv.y; acc[28 + q * 4 + 1] += v1 * wv.y;
                acc[q * 4 + 2] += v0 * wv.z; acc[28 + q * 4 + 2] += v1 * wv.z;
                acc[q * 4 + 3] += v0 * wv.w; acc[28 + q * 4 + 3] += v1 * wv.w;
            }
        }
    }

    __syncthreads();   // all groups done reading sw
    if (g > 0) {
        float* pb = part + (g - 1) * 3456;
#pragma unroll
        for (int j = 0; j < 27; j++) {
            pb[j * 128 + px]      = acc[j];
            pb[j * 128 + px + 64] = acc[28 + j];
        }
    }
    __syncthreads();
    if (g == 0) {
#pragma unroll
        for (int j = 0; j < 27; j++) {
            float a0 = acc[j], a1 = acc[28 + j];
#pragma unroll
            for (int i = 0; i < 5; i++) {
                a0 += part[i * 3456 + j * 128 + px];
                a1 += part[i * 3456 + j * 128 + px + 64];
            }
            if (j < 9) {
                float bse = y * inv + (float)(j / 3 - 1);
                idx_out[((b * 18 + j) * Hh + y) * Ww + px]      = bse + a0;
                idx_out[((b * 18 + j) * Hh + y) * Ww + px + 64] = bse + a1;
                omb[j * 128 + px] = a0; omb[j * 128 + px + 64] = a1;
            } else if (j < 18) {
                int j2 = j - 9;
                float c0 = (float)px * inv - 0.5f + (float)(j2 % 3 - 1);
                float c1 = (float)(px + 64) * inv - 0.5f + (float)(j2 % 3 - 1);
                idx_out[((b * 18 + j) * Hh + y) * Ww + px]      = c0 + a0;
                idx_out[((b * 18 + j) * Hh + y) * Ww + px + 64] = c1 + a1;
                omb[j * 128 + px] = a0; omb[j * 128 + px + 64] = a1;
            } else {
                float s0 = 1.0f / (1.0f + __expf(-a0));
                float s1 = 1.0f / (1.0f + __expf(-a1));
                mask_out[((b * 9 + (j - 18)) * Hh + y) * Ww + px]      = s0;
                mask_out[((b * 9 + (j - 18)) * Hh + y) * Ww + px + 64] = s1;
                omb[j * 128 + px] = s0; omb[j * 128 + px + 64] = s1;
            }
        }
    }
    __syncthreads();

    // ---- phase C: packed corner tables (overwrites sw region) ----
    for (int q = tid; q < 9 * 128; q += 384) {
        int t = q >> 7;
        int p = q & 127;
        float oh = omb[(2 * t) * 128 + p];
        float ow = omb[(2 * t + 1) * 128 + p];
        float mk = omb[(18 + t) * 128 + p];

        float ph = oh + (float)(t / 3) + (float)(y - 1);
        float pw = ow + (float)(t % 3) + (float)(p - 1);
        float h0f = floorf(ph), w0f = floorf(pw);
        float lh = ph - h0f, lw = pw - w0f;
        float hh = 1.0f - lh, hw = 1.0f - lw;
        int h0 = (int)h0f, w0 = (int)w0f;
        int h1 = h0 + 1,   w1 = w0 + 1;
        float okh0 = (h0 >= 0 && h0 < Hh) ? 1.0f : 0.0f;
        float okh1 = (h1 >= 0 && h1 < Hh) ? 1.0f : 0.0f;
        float okw0 = (w0 >= 0 && w0 < Ww) ? 1.0f : 0.0f;
        float okw1 = (w1 >= 0 && w1 < Ww) ? 1.0f : 0.0f;
        float w00 = hh * hw * okh0 * okw0 * mk;
        float w01 = hh * lw * okh0 * okw1 * mk;
        float w10 = lh * hw * okh1 * okw0 * mk;
        float w11 = lh * lw * okh1 * okw1 * mk;
        int h0c = min(max(h0, 0), Hh - 1), h1c = min(max(h1, 0), Hh - 1);
        int w0c = min(max(w0, 0), Ww - 1), w1c = min(max(w1, 0), Ww - 1);

        sWt[q] = make_float4(w00, w01, w10, w11);
        sPk[q] = (h0c * 128 + w0c) | ((h1c - h0c) << 14) | ((w1c - w0c) << 15);
    }
    __syncthreads();

    // ---- phase D: producers gather 16-ch chunks; consumers mma.sync ----
    const float* binp = input + b * Cin * HW;

    if (tid >= 256) {
        // producers (warps 8-11): one pixel per thread; 16 channels per chunk
        const int ptid = tid - 256;

        auto produce = [&](int cn, int buf) {
            __half* dst = cols + buf * BUFH + ptid;
            if (cn < 4) {
                const float* pl0 = binp + (16 * cn) * HW;
#pragma unroll
                for (int t = 0; t < 9; t++) {
                    int    pk = sPk[t * 128 + ptid];
                    float4 wt = sWt[t * 128 + ptid];
                    int a00 = pk & 0x3FFF;
                    int a10 = a00 + ((pk & 0x4000) >> 7);   // +128 if dh
                    int dw  = (pk >> 15) & 1;
                    int a01 = a00 + dw, a11 = a10 + dw;
                    const float* pl = pl0;
#pragma unroll
                    for (int cc = 0; cc < 16; cc++, pl += HW) {
                        float v = wt.x * pl[a00] + wt.y * pl[a01]
                                + wt.z * pl[a10] + wt.w * pl[a11];
                        dst[(cc * 9 + t) * RS] = __float2half_rn(v);
                    }
                }
            } else {
                // tail: rows 0..8 = h-coord (k 576..584), 9..17 = w-coord,
                // rows 18..63 = zero (k 594..639)
#pragma unroll
                for (int t = 0; t < 9; t++) {
                    int    pk = sPk[t * 128 + ptid];
                    float4 wt = sWt[t * 128 + ptid];
                    int a00 = pk & 0x3FFF;
                    float h0c = (float)(a00 >> 7), w0c = (float)(a00 & 127);
                    float h1c = h0c + (float)((pk >> 14) & 1);
                    float w1c = w0c + (float)((pk >> 15) & 1);
                    dst[t * RS] = __float2half_rn(
                        ((wt.x + wt.y) * h0c + (wt.z + wt.w) * h1c) * inv);
                    dst[(9 + t) * RS] = __float2half_rn(
                          (wt.x + wt.z) * (w0c * inv - 0.5f)
                        + (wt.y + wt.w) * (w1c * inv - 0.5f));
                }
#pragma unroll
                for (int s = 18; s < 64; s++) dst[s * RS] = __ushort_as_half(0);
            }
        };

        produce(0, 0);
        __syncthreads();
        for (int c = 0; c < NCH; c++) {
            if (c + 1 < NCH) produce(c + 1, (c + 1) & 1);
            __syncthreads();
        }
    } else {
        // consumers (warps 0-7): mma.sync m16n8k16; warp = 16 px x 64 oc
        const int lane = tid & 31;
        const int m0   = (tid >> 5) * 16;
        const int r    = lane & 7;
        const int kofs = (lane & 16) ? 8 : 0;
        const int mofs = (lane & 8)  ? 8 : 0;
        const uint32_t cbase = smem_u32(cols);
        // byte offset of this thread's ldmatrix row within a chunk buffer
        const uint32_t off0 = (uint32_t)(((kofs + r) * RS + m0 + mofs) * 2);

        float dacc[8][4];
#pragma unroll
        for (int i = 0; i < 8; i++)
#pragma unroll
            for (int j = 0; j < 4; j++) dacc[i][j] = 0.0f;

        __syncthreads();   // matches producer's post-produce(0) barrier
        for (int c = 0; c < NCH; c++) {
            const uint32_t bufa = cbase + (uint32_t)((c & 1) * (BUFH * 2)) + off0;
            const int nks = (c < 4) ? 9 : 4;
            for (int ks = 0; ks < nks; ks++) {
                uint32_t a0, a1, a2, a3;
                uint32_t addr = bufa + (uint32_t)(ks * 16 * RS * 2);
                asm volatile(
                    "ldmatrix.sync.aligned.m8n8.x4.trans.shared.b16 "
                    "{%0,%1,%2,%3}, [%4];"
                    : "=r"(a0), "=r"(a1), "=r"(a2), "=r"(a3) : "r"(addr));
                const uint2* wfp = g_wfrag + (c * 9 + ks) * 256 + lane;
#pragma unroll
                for (int nf = 0; nf < 8; nf++) {
                    uint2 bv = __ldg(wfp + nf * 32);
                    asm volatile(
                        "mma.sync.aligned.m16n8k16.row.col.f32.f16.f16.f32 "
                        "{%0,%1,%2,%3}, {%4,%5,%6,%7}, {%8,%9}, {%0,%1,%2,%3};"
                        : "+f"(dacc[nf][0]), "+f"(dacc[nf][1]),
                          "+f"(dacc[nf][2]), "+f"(dacc[nf][3])
                        : "r"(a0), "r"(a1), "r"(a2), "r"(a3),
                          "r"(bv.x), "r"(bv.y));
                }
            }
            __syncthreads();
        }

        // writeback: lane holds D[m0 + lane/4][nf*8 + 2*(lane%3..)] pairs
        const int m  = lane >> 2;
        const int np = (lane & 3) * 2;
#pragma unroll
        for (int nf = 0; nf < 8; nf++) {
            int oc = nf * 8 + np;
            float b0v = __ldg(bias + oc);
            float b1v = __ldg(bias + oc + 1);
            float* o0 = out + ((b * Cout + oc)     * Hh + y) * Ww;
            float* o1 = out + ((b * Cout + oc + 1) * Hh + y) * Ww;
            o0[m0 + m]     = dacc[nf][0] + b0v;
            o1[m0 + m]     = dacc[nf][1] + b1v;
            o0[m0 + m + 8] = dacc[nf][2] + b0v;
            o1[m0 + m + 8] = dacc[nf][3] + b1v;
        }
    }
}

// ---------------- launcher ----------------
extern "C" void kernel_launch(void* const* d_in, const int* in_sizes, int n_in,
                              void* d_out, int out_size)
{
    const float* input  = (const float*)d_in[0];
    const float* weight = (const float*)d_in[1];
    const float* bias   = (const float*)d_in[2];
    const float* w_om   = (const float*)d_in[3];
    const float* b_om   = (const float*)d_in[4];

    float* out      = (float*)d_out;
    float* idx_out  = out + (size_t)Bn * Cout * Hh * Ww;
    float* mask_out = idx_out + (size_t)Bn * 18 * Hh * Ww;

    const int smF = 5760 * 4 + 2 * BUFH * 2;   // 23040 + 78336 = 101,376 B
    cudaFuncSetAttribute(fused_kernel, cudaFuncAttributeMaxDynamicSharedMemorySize, smF);

    prep_wfrag_kernel<<<(NKSTEP * 256 + 255) / 256, 256>>>(weight);
    fused_kernel<<<dim3(Hh, Bn), 384, smF>>>(input, w_om, b_om, bias,
                                             out, idx_out, mask_out);
}

// round 16
// speedup vs baseline: 8.2627x; 1.4602x over previous
#include <cuda_runtime.h>
#include <cuda_fp16.h>
#include <cstdint>

#define Bn   8
#define Cin  64
#define Hh   128
#define Ww   128
#define HW   (Hh*Ww)
#define Cout 64
#define CIN2 66
#define KDIM 594    // CIN2 * 9
#define NCH  5      // 4 chunks x 144 k (16 ch) + 1 tail chunk (2 ch -> 2 ksteps)
#define RS   136    // cols row stride in halves (272 B -> conflict-free ldmatrix)
#define BUFH (144*RS)
#define NKS  38     // 4*9 + 2 ksteps

// ---------------- scratch: pre-packed B fragments (mma.m16n8k16) ----------------
__device__ uint2 g_wfrag   [NKS*8*32];   // main weight, N=64
__device__ uint2 g_wfrag_om[NKS*4*32];   // om weight,   N=27 (padded 32)

__global__ void prep_wfrag_kernel(const float* __restrict__ w,
                                  const float* __restrict__ w_om)
{
    int i = blockIdx.x * 256 + threadIdx.x;
    const int main_total = NKS * 256;
    if (i < main_total) {
        int kstep = i >> 8, rem = i & 255;
        int nfrag = rem >> 5, lane = rem & 31;
        int n  = nfrag * 8 + (lane >> 2);
        int kb = kstep * 16 + (lane & 3) * 2;
        auto B = [&](int k) -> uint32_t {
            float v = (k < KDIM) ? w[n * KDIM + k] : 0.0f;
            return (uint32_t)__half_as_ushort(__float2half_rn(v));
        };
        g_wfrag[i] = make_uint2(B(kb) | (B(kb+1) << 16), B(kb+8) | (B(kb+9) << 16));
    } else if (i < main_total + NKS * 128) {
        int j = i - main_total;
        int kstep = j >> 7, rem = j & 127;
        int nfrag = rem >> 5, lane = rem & 31;
        int n  = nfrag * 8 + (lane >> 2);
        int kb = kstep * 16 + (lane & 3) * 2;
        auto B = [&](int k) -> uint32_t {
            float v = (n < 27 && k < KDIM) ? w_om[n * KDIM + k] : 0.0f;
            return (uint32_t)__half_as_ushort(__float2half_rn(v));
        };
        g_wfrag_om[j] = make_uint2(B(kb) | (B(kb+1) << 16), B(kb+8) | (B(kb+9) << 16));
    }
}

__device__ __forceinline__ uint32_t smem_u32(const void* p) {
    uint32_t a;
    asm("{ .reg .u64 t; cvta.to.shared.u64 t, %1; cvt.u32.u64 %0, t; }"
        : "=r"(a) : "l"(p));
    return a;
}

// ---------------- fused kernel ----------------
// One block per (row y, batch b); 384 threads.
// Phase B: om conv via mma (producers fill regular im2col, consumers mma vs
//          g_wfrag_om), writeback -> ombo (fp16 offsets) / ombm (fp32 mask)
//          + idx/mask outputs.
// Phase C: packed corner tables. Phase D: deformable gather + mma (as R13).
// Smem bytes: sWt[0,18432) sPk[18432,23040) cols[23040,101376)
//             ombo[101376,105984) ombm[105984,110592)
__global__ void __launch_bounds__(384, 2) fused_kernel(
    const float* __restrict__ input,
    const float* __restrict__ b_om,
    const float* __restrict__ bias,
    float* __restrict__ out,
    float* __restrict__ idx_out,
    float* __restrict__ mask_out)
{
    extern __shared__ float sm[];
    float4* sWt  = (float4*)sm;               // [1152]
    int*    sPk  = (int*)(sm + 4608);         // [1152]
    __half* cols = (__half*)(sm + 5760);      // [2][144][136]
    __half* ombo = (__half*)(sm + 25344);     // [18][128] offsets
    float*  ombm = sm + 26496;                // [9][128]  mask

    const int tid = threadIdx.x;
    const int y   = blockIdx.x;
    const int b   = blockIdx.y;
    const float inv = 1.0f / 128.0f;

    const int lane = tid & 31;
    const uint32_t cbase = smem_u32(cols);
    // consumer ldmatrix source offset (same mapping proven in R13)
    const int m0   = (tid >> 5) * 16;
    const int r    = lane & 7;
    const int kofs = (lane & 16) ? 8 : 0;
    const int mofs = (lane & 8)  ? 8 : 0;
    const uint32_t off0 = (uint32_t)(((kofs + r) * RS + m0 + mofs) * 2);

    const float* binp = input + b * Cin * HW;

    // ================= phase B: om conv via mma =================
    if (tid >= 256) {
        // producers: regular im2col fill (shifted rows), 16 ch per chunk
        const int ptid = tid - 256;   // pixel

        auto produce_om = [&](int cn, int buf) {
            __half* dst = cols + buf * BUFH + ptid;
            if (cn < 4) {
#pragma unroll
                for (int cc = 0; cc < 16; cc++) {
                    const float* base = binp + (16 * cn + cc) * HW;
#pragma unroll
                    for (int dy = 0; dy < 3; dy++) {
                        int yy = y + dy - 1;
                        bool yok = (yy >= 0 && yy < Hh);
                        const float* rp = base + yy * Ww;
#pragma unroll
                        for (int dx = 0; dx < 3; dx++) {
                            int xx = ptid + dx - 1;
                            float v = (yok && xx >= 0 && xx < Ww) ? rp[xx] : 0.0f;
                            dst[(cc * 9 + dy * 3 + dx) * RS] = __float2half_rn(v);
                        }
                    }
                }
            } else {
                // ch 64 = h-coord, ch 65 = w-coord (conv zero padding!)
#pragma unroll
                for (int dy = 0; dy < 3; dy++) {
                    int yy = y + dy - 1;
                    bool yok = (yy >= 0 && yy < Hh);
#pragma unroll
                    for (int dx = 0; dx < 3; dx++) {
                        int xx = ptid + dx - 1;
                        bool ok = yok && xx >= 0 && xx < Ww;
                        dst[(dy * 3 + dx) * RS] =
                            __float2half_rn(ok ? yy * inv : 0.0f);
                        dst[(9 + dy * 3 + dx) * RS] =
                            __float2half_rn(ok ? xx * inv - 0.5f : 0.0f);
                    }
                }
#pragma unroll
                for (int s = 18; s < 32; s++) dst[s * RS] = __ushort_as_half(0);
            }
        };

        produce_om(0, 0);
        __syncthreads();
        for (int c = 0; c < NCH; c++) {
            if (c + 1 < NCH) produce_om(c + 1, (c + 1) & 1);
            __syncthreads();
        }
    } else {
        // consumers: mma vs om fragments; warp = 16 px x 32 oc
        float dacc[4][4];
#pragma unroll
        for (int i = 0; i < 4; i++)
#pragma unroll
            for (int j = 0; j < 4; j++) dacc[i][j] = 0.0f;

        __syncthreads();
        for (int c = 0; c < NCH; c++) {
            const uint32_t bufa = cbase + (uint32_t)((c & 1) * (BUFH * 2)) + off0;
            const int nks = (c < 4) ? 9 : 2;
            for (int ks = 0; ks < nks; ks++) {
                uint32_t a0, a1, a2, a3;
                uint32_t addr = bufa + (uint32_t)(ks * 16 * RS * 2);
                asm volatile(
                    "ldmatrix.sync.aligned.m8n8.x4.trans.shared.b16 "
                    "{%0,%1,%2,%3}, [%4];"
                    : "=r"(a0), "=r"(a1), "=r"(a2), "=r"(a3) : "r"(addr));
                const uint2* wfp = g_wfrag_om + (c * 9 + ks) * 128 + lane;
#pragma unroll
                for (int nf = 0; nf < 4; nf++) {
                    uint2 bv = __ldg(wfp + nf * 32);
                    asm volatile(
                        "mma.sync.aligned.m16n8k16.row.col.f32.f16.f16.f32 "
                        "{%0,%1,%2,%3}, {%4,%5,%6,%7}, {%8,%9}, {%0,%1,%2,%3};"
                        : "+f"(dacc[nf][0]), "+f"(dacc[nf][1]),
                          "+f"(dacc[nf][2]), "+f"(dacc[nf][3])
                        : "r"(a0), "r"(a1), "r"(a2), "r"(a3),
                          "r"(bv.x), "r"(bv.y));
                }
            }
            __syncthreads();
        }

        // writeback om results
        const int m  = lane >> 2;
        const int np = (lane & 3) * 2;
        const int pix0 = m0 + m, pix1 = m0 + m + 8;
#pragma unroll
        for (int nf = 0; nf < 4; nf++) {
#pragma unroll
            for (int h = 0; h < 2; h++) {
                int oc = nf * 8 + np + h;
                if (oc >= 27) continue;
                float bv = __ldg(b_om + oc);
                float a0 = dacc[nf][h]     + bv;
                float a1 = dacc[nf][2 + h] + bv;
                if (oc < 18) {
                    ombo[oc * 128 + pix0] = __float2half_rn(a0);
                    ombo[oc * 128 + pix1] = __float2half_rn(a1);
                    float b0, b1;
                    if (oc < 9) {
                        b0 = b1 = y * inv + (float)(oc / 3 - 1);
                    } else {
                        float cc = -0.5f + (float)((oc - 9) % 3 - 1);
                        b0 = pix0 * inv + cc;
                        b1 = pix1 * inv + cc;
                    }
                    float* ip = idx_out + ((b * 18 + oc) * Hh + y) * Ww;
                    ip[pix0] = b0 + a0;
                    ip[pix1] = b1 + a1;
                } else {
                    float s0 = 1.0f / (1.0f + __expf(-a0));
                    float s1 = 1.0f / (1.0f + __expf(-a1));
                    ombm[(oc - 18) * 128 + pix0] = s0;
                    ombm[(oc - 18) * 128 + pix1] = s1;
                    float* mp = mask_out + ((b * 9 + oc - 18) * Hh + y) * Ww;
                    mp[pix0] = s0;
                    mp[pix1] = s1;
                }
            }
        }
    }
    __syncthreads();

    // ================= phase C: packed corner tables =================
    for (int q = tid; q < 9 * 128; q += 384) {
        int t = q >> 7;
        int p = q & 127;
        float oh = __half2float(ombo[(2 * t) * 128 + p]);
        float ow = __half2float(ombo[(2 * t + 1) * 128 + p]);
        float mk = ombm[t * 128 + p];

        float ph = oh + (float)(t / 3) + (float)(y - 1);
        float pw = ow + (float)(t % 3) + (float)(p - 1);
        float h0f = floorf(ph), w0f = floorf(pw);
        float lh = ph - h0f, lw = pw - w0f;
        float hh = 1.0f - lh, hw = 1.0f - lw;
        int h0 = (int)h0f, w0 = (int)w0f;
        int h1 = h0 + 1,   w1 = w0 + 1;
        float okh0 = (h0 >= 0 && h0 < Hh) ? 1.0f : 0.0f;
        float okh1 = (h1 >= 0 && h1 < Hh) ? 1.0f : 0.0f;
        float okw0 = (w0 >= 0 && w0 < Ww) ? 1.0f : 0.0f;
        float okw1 = (w1 >= 0 && w1 < Ww) ? 1.0f : 0.0f;
        float w00 = hh * hw * okh0 * okw0 * mk;
        float w01 = hh * lw * okh0 * okw1 * mk;
        float w10 = lh * hw * okh1 * okw0 * mk;
        float w11 = lh * lw * okh1 * okw1 * mk;
        int h0c = min(max(h0, 0), Hh - 1), h1c = min(max(h1, 0), Hh - 1);
        int w0c = min(max(w0, 0), Ww - 1), w1c = min(max(w1, 0), Ww - 1);

        sWt[q] = make_float4(w00, w01, w10, w11);
        sPk[q] = (h0c * 128 + w0c) | ((h1c - h0c) << 14) | ((w1c - w0c) << 15);
    }
    __syncthreads();

    // ================= phase D: deformable gather + mma =================
    if (tid >= 256) {
        // producers: one pixel per thread; 16 channels per chunk
        const int ptid = tid - 256;

        auto produce = [&](int cn, int buf) {
            __half* dst = cols + buf * BUFH + ptid;
            if (cn < 4) {
                const float* pl0 = binp + (16 * cn) * HW;
#pragma unroll
                for (int t = 0; t < 9; t++) {
                    int    pk = sPk[t * 128 + ptid];
                    float4 wt = sWt[t * 128 + ptid];
                    int a00 = pk & 0x3FFF;
                    int a10 = a00 + ((pk & 0x4000) >> 7);   // +128 if dh
                    int dw  = (pk >> 15) & 1;
                    int a01 = a00 + dw, a11 = a10 + dw;
                    const float* pl = pl0;
#pragma unroll
                    for (int cc = 0; cc < 16; cc++, pl += HW) {
                        float v = wt.x * pl[a00] + wt.y * pl[a01]
                                + wt.z * pl[a10] + wt.w * pl[a11];
                        dst[(cc * 9 + t) * RS] = __float2half_rn(v);
                    }
                }
            } else {
                // tail: deformed coordinate channels + zero pad
#pragma unroll
                for (int t = 0; t < 9; t++) {
                    int    pk = sPk[t * 128 + ptid];
                    float4 wt = sWt[t * 128 + ptid];
                    int a00 = pk & 0x3FFF;
                    float h0c = (float)(a00 >> 7), w0c = (float)(a00 & 127);
                    float h1c = h0c + (float)((pk >> 14) & 1);
                    float w1c = w0c + (float)((pk >> 15) & 1);
                    dst[t * RS] = __float2half_rn(
                        ((wt.x + wt.y) * h0c + (wt.z + wt.w) * h1c) * inv);
                    dst[(9 + t) * RS] = __float2half_rn(
                          (wt.x + wt.z) * (w0c * inv - 0.5f)
                        + (wt.y + wt.w) * (w1c * inv - 0.5f));
                }
#pragma unroll
                for (int s = 18; s < 32; s++) dst[s * RS] = __ushort_as_half(0);
            }
        };

        produce(0, 0);
        __syncthreads();
        for (int c = 0; c < NCH; c++) {
            if (c + 1 < NCH) produce(c + 1, (c + 1) & 1);
            __syncthreads();
        }
    } else {
        // consumers: mma m16n8k16; warp = 16 px x 64 oc
        float dacc[8][4];
#pragma unroll
        for (int i = 0; i < 8; i++)
#pragma unroll
            for (int j = 0; j < 4; j++) dacc[i][j] = 0.0f;

        __syncthreads();
        for (int c = 0; c < NCH; c++) {
            const uint32_t bufa = cbase + (uint32_t)((c & 1) * (BUFH * 2)) + off0;
            const int nks = (c < 4) ? 9 : 2;
            for (int ks = 0; ks < nks; ks++) {
                uint32_t a0, a1, a2, a3;
                uint32_t addr = bufa + (uint32_t)(ks * 16 * RS * 2);
                asm volatile(
                    "ldmatrix.sync.aligned.m8n8.x4.trans.shared.b16 "
                    "{%0,%1,%2,%3}, [%4];"
                    : "=r"(a0), "=r"(a1), "=r"(a2), "=r"(a3) : "r"(addr));
                const uint2* wfp = g_wfrag + (c * 9 + ks) * 256 + lane;
#pragma unroll
                for (int nf = 0; nf < 8; nf++) {
                    uint2 bv = __ldg(wfp + nf * 32);
                    asm volatile(
                        "mma.sync.aligned.m16n8k16.row.col.f32.f16.f16.f32 "
                        "{%0,%1,%2,%3}, {%4,%5,%6,%7}, {%8,%9}, {%0,%1,%2,%3};"
                        : "+f"(dacc[nf][0]), "+f"(dacc[nf][1]),
                          "+f"(dacc[nf][2]), "+f"(dacc[nf][3])
                        : "r"(a0), "r"(a1), "r"(a2), "r"(a3),
                          "r"(bv.x), "r"(bv.y));
                }
            }
            __syncthreads();
        }

        // writeback
        const int m  = lane >> 2;
        const int np = (lane & 3) * 2;
#pragma unroll
        for (int nf = 0; nf < 8; nf++) {
            int oc = nf * 8 + np;
            float b0v = __ldg(bias + oc);
            float b1v = __ldg(bias + oc + 1);
            float* o0 = out + ((b * Cout + oc)     * Hh + y) * Ww;
            float* o1 = out + ((b * Cout + oc + 1) * Hh + y) * Ww;
            o0[m0 + m]     = dacc[nf][0] + b0v;
            o1[m0 + m]     = dacc[nf][1] + b1v;
            o0[m0 + m + 8] = dacc[nf][2] + b0v;
            o1[m0 + m + 8] = dacc[nf][3] + b1v;
        }
    }
}

// ---------------- launcher ----------------
extern "C" void kernel_launch(void* const* d_in, const int* in_sizes, int n_in,
                              void* d_out, int out_size)
{
    const float* input  = (const float*)d_in[0];
    const float* weight = (const float*)d_in[1];
    const float* bias   = (const float*)d_in[2];
    const float* w_om   = (const float*)d_in[3];
    const float* b_om   = (const float*)d_in[4];

    float* out      = (float*)d_out;
    float* idx_out  = out + (size_t)Bn * Cout * Hh * Ww;
    float* mask_out = idx_out + (size_t)Bn * 18 * Hh * Ww;

    const int smF = 110592;   // bytes (see layout comment)
    cudaFuncSetAttribute(fused_kernel, cudaFuncAttributeMaxDynamicSharedMemorySize, smF);

    prep_wfrag_kernel<<<(NKS * 256 + NKS * 128 + 255) / 256, 256>>>(weight, w_om);
    fused_kernel<<<dim3(Hh, Bn), 384, smF>>>(input, b_om, bias,
                                             out, idx_out, mask_out);
}